// round 5
// baseline (speedup 1.0000x reference)
#include <cuda_runtime.h>

#define N_PTS   8192
#define C_DIM   64
#define C4      (C_DIM/4)          // 16 float4 per row
#define NQ      (3*N_PTS)          // 24576 query points
#define VOFF    ((size_t)4*N_PTS*C_DIM)  // float offset of out_coords = 2097152

#define TPB     256
#define QPB     128                // queries per block
#define SEGLEN  (N_PTS/2)          // each thread scans half the points
#define SMEM_BYTES ((3*N_PTS + QPB)*4 + QPB*4*2)   // 99840

// ---------------------------------------------------------------------------
// Kernel 1: copy values -> out_values[0:N], build all 4N coordinate rows.
// Bit-exactness: x+spacing done with __fadd_rn (round-to-nearest, no fusion).
// ---------------------------------------------------------------------------
__global__ void setup_kernel(const float4* __restrict__ val4,
                             const float2* __restrict__ c2,
                             const float*  __restrict__ spacing,
                             float*        __restrict__ out)
{
    int tid    = blockIdx.x * blockDim.x + threadIdx.x;
    int stride = gridDim.x * blockDim.x;

    float4* outv4 = reinterpret_cast<float4*>(out);
    for (int i = tid; i < N_PTS * C4; i += stride)
        outv4[i] = __ldg(&val4[i]);

    float s0 = __ldg(&spacing[0]);
    float s1 = __ldg(&spacing[1]);
    float2* outc = reinterpret_cast<float2*>(out + VOFF);
    for (int i = tid; i < N_PTS; i += stride) {
        float2 c = __ldg(&c2[i]);
        float xs = __fadd_rn(c.x, s0);
        float ys = __fadd_rn(c.y, s1);
        outc[i]             = c;                       // original coords
        outc[N_PTS   + i]   = make_float2(xs,  ys);    // group 0: (x+s0, y+s1)
        outc[2*N_PTS + i]   = make_float2(c.x, ys);    // group 1: (x,    y+s1)
        outc[3*N_PTS + i]   = make_float2(xs,  c.y);   // group 2: (x+s0, y)
    }
}

// d2 exactly as the reference computes it:
//   (sa + sc) - (2a)@c  with the K=2 dot fma-accumulated k-ascending.
// (2.0*a)@c == 2*((a@c)) bitwise since doubling is exact, so we fold the 2
// into an exact m+m.
__device__ __forceinline__ float dcalc(float a0, float a1, float sa,
                                       float cx, float cy, float scj)
{
    float m  = fmaf(a1, cy, __fmul_rn(a0, cx));
    float m2 = __fadd_rn(m, m);
    return __fsub_rn(__fadd_rn(sa, scj), m2);
}

extern __shared__ float smem_dyn[];

// ---------------------------------------------------------------------------
// Kernel 2: per-query argmin over all 8192 points + fused value-row gather.
// Block = 128 queries x 2 j-segments. All lanes of a warp share the same
// segment -> smem loads are pure broadcast (float4, SoA).
// Tie-breaking everywhere is strict '<' with ascending indices == jnp.argmin
// first-occurrence semantics.
// ---------------------------------------------------------------------------
__global__ void __launch_bounds__(TPB, 2)
argmin_gather_kernel(const float2* __restrict__ c2,
                     const float*  __restrict__ spacing,
                     const float*  __restrict__ shift,
                     const float4* __restrict__ val4,
                     float*        __restrict__ out)
{
    float* c0   = smem_dyn;
    float* c1   = c0 + N_PTS;
    float* sc   = c1 + N_PTS;
    float* rd   = sc + N_PTS;                 // QPB floats: seg-1 partial d2
    int*   ri   = reinterpret_cast<int*>(rd + QPB);   // QPB ints: seg-1 idx
    int*   widx = ri + QPB;                   // QPB ints: winning indices

    // Stage coords + |c|^2 (reference order: c0*c0 + c1*c1, mul then add)
    for (int i = threadIdx.x; i < N_PTS; i += TPB) {
        float2 c = __ldg(&c2[i]);
        c0[i] = c.x;
        c1[i] = c.y;
        sc[i] = __fadd_rn(__fmul_rn(c.x, c.x), __fmul_rn(c.y, c.y));
    }
    __syncthreads();

    int r   = threadIdx.x & (QPB - 1);
    int seg = threadIdx.x >> 7;               // 0: j in [0,4096), 1: [4096,8192)
    int q   = blockIdx.x * QPB + r;            // global query id, 0..24575
    int g   = q >> 13;                         // which of the 3 shifted copies
    int i   = q & (N_PTS - 1);

    float2 c  = __ldg(&c2[i]);
    float s0  = __ldg(&spacing[0]), s1  = __ldg(&spacing[1]);
    float sh0 = __ldg(&shift[0]),   sh1 = __ldg(&shift[1]);

    float nc0, nc1;
    if (g == 0)      { nc0 = __fadd_rn(c.x, s0); nc1 = __fadd_rn(c.y, s1); }
    else if (g == 1) { nc0 = c.x;                nc1 = __fadd_rn(c.y, s1); }
    else             { nc0 = __fadd_rn(c.x, s0); nc1 = c.y;                }

    float a0 = __fsub_rn(nc0, sh0);
    float a1 = __fsub_rn(nc1, sh1);
    float sa = __fadd_rn(__fmul_rn(a0, a0), __fmul_rn(a1, a1));

    float bd = __int_as_float(0x7f800000);     // +inf
    int   bj = 0;
    const int jbeg = seg * SEGLEN;

    #pragma unroll 1
    for (int t = 0; t < SEGLEN; t += 8) {
        int j = jbeg + t;
        float4 x0 = *reinterpret_cast<const float4*>(&c0[j]);
        float4 x1 = *reinterpret_cast<const float4*>(&c0[j + 4]);
        float4 y0 = *reinterpret_cast<const float4*>(&c1[j]);
        float4 y1 = *reinterpret_cast<const float4*>(&c1[j + 4]);
        float4 z0 = *reinterpret_cast<const float4*>(&sc[j]);
        float4 z1 = *reinterpret_cast<const float4*>(&sc[j + 4]);

        float d0 = dcalc(a0, a1, sa, x0.x, y0.x, z0.x);
        float d1 = dcalc(a0, a1, sa, x0.y, y0.y, z0.y);
        float d2 = dcalc(a0, a1, sa, x0.z, y0.z, z0.z);
        float d3 = dcalc(a0, a1, sa, x0.w, y0.w, z0.w);
        float d4 = dcalc(a0, a1, sa, x1.x, y1.x, z1.x);
        float d5 = dcalc(a0, a1, sa, x1.y, y1.y, z1.y);
        float d6 = dcalc(a0, a1, sa, x1.z, y1.z, z1.z);
        float d7 = dcalc(a0, a1, sa, x1.w, y1.w, z1.w);

        // 8-way tournament; strict '<' + ascending indices => first-min wins
        bool p01 = d1 < d0;  float e0 = p01 ? d1 : d0;  int k0 = p01 ? 1 : 0;
        bool p23 = d3 < d2;  float e1 = p23 ? d3 : d2;  int k1 = p23 ? 3 : 2;
        bool p45 = d5 < d4;  float e2 = p45 ? d5 : d4;  int k2 = p45 ? 5 : 4;
        bool p67 = d7 < d6;  float e3 = p67 ? d7 : d6;  int k3 = p67 ? 7 : 6;
        bool q0  = e1 < e0;  float f0 = q0 ? e1 : e0;   int l0 = q0 ? k1 : k0;
        bool q1  = e3 < e2;  float f1 = q1 ? e3 : e2;   int l1 = q1 ? k3 : k2;
        bool w0  = f1 < f0;  float g0d = w0 ? f1 : f0;  int gk = w0 ? l1 : l0;

        bool pw = g0d < bd;
        bd = pw ? g0d : bd;
        bj = pw ? (j + gk) : bj;
    }

    // Cross-segment reduce: seg-1 indices are all larger, so strict '<'
    // keeps seg-0 on ties (first occurrence).
    if (seg == 1) { rd[r] = bd; ri[r] = bj; }
    __syncthreads();
    if (seg == 0) {
        float dh = rd[r];
        int   ih = ri[r];
        if (dh < bd) { bd = dh; bj = ih; }
        widx[r] = bj;
    }
    __syncthreads();

    // Fused gather: copy values[widx[r]] (64 f32 = 16 f4) to out row N+q.
    int qbase = blockIdx.x * QPB;
    float4* outv4 = reinterpret_cast<float4*>(out);
    for (int t = threadIdx.x; t < QPB * C4; t += TPB) {
        int rr = t >> 4;
        int cc = t & (C4 - 1);
        outv4[(size_t)(N_PTS + qbase + rr) * C4 + cc] =
            __ldg(&val4[(size_t)widx[rr] * C4 + cc]);
    }
}

// ---------------------------------------------------------------------------
extern "C" void kernel_launch(void* const* d_in, const int* in_sizes, int n_in,
                              void* d_out, int out_size)
{
    const float4* val4    = (const float4*)d_in[0];   // values  (8192*64)
    const float2* c2      = (const float2*)d_in[1];   // coords  (8192*2)
    const float*  spacing = (const float*) d_in[2];   // (2,)
    const float*  shift   = (const float*) d_in[3];   // (2,)
    float* out = (float*)d_out;

    cudaFuncSetAttribute(argmin_gather_kernel,
                         cudaFuncAttributeMaxDynamicSharedMemorySize,
                         SMEM_BYTES);

    setup_kernel<<<256, TPB>>>(val4, c2, spacing, out);
    argmin_gather_kernel<<<NQ / QPB, TPB, SMEM_BYTES>>>(c2, spacing, shift,
                                                        val4, out);
}

// round 6
// speedup vs baseline: 1.8672x; 1.8672x over previous
#include <cuda_runtime.h>

#define N_PTS   8192
#define C_DIM   64
#define C4      (C_DIM/4)
#define NQ      (3*N_PTS)                 // 24576 queries
#define VOFF    ((size_t)4*N_PTS*C_DIM)   // float offset of out_coords

#define TPB     256
#define NSEG    6
#define SEGSZ   1368                      // segs 0..4 = 1368 pts, seg 5 = 1352
#define QCTA    (NQ/TPB)                  // 96 CTAs per segment
#define GRID1   (NSEG*QCTA)               // 576 CTAs = one wave at 4/SM
#define SMEM1   (3*SEGSZ*4)               // 16416 B

typedef unsigned long long u64;

// Cross-CTA partial argmin scratch (static device globals are allowed).
__device__ float g_pd[NSEG * NQ];
__device__ int   g_pj[NSEG * NQ];

// ---------------- packed f32x2 helpers (IEEE RN per lane, no ftz) ----------
__device__ __forceinline__ u64 pk2(float lo, float hi) {
    u64 r; asm("mov.b64 %0,{%1,%2};" : "=l"(r) : "f"(lo), "f"(hi)); return r;
}
__device__ __forceinline__ void upk2(float& lo, float& hi, u64 v) {
    asm("mov.b64 {%0,%1},%2;" : "=f"(lo), "=f"(hi) : "l"(v));
}
__device__ __forceinline__ u64 mul2(u64 a, u64 b) {
    u64 r; asm("mul.rn.f32x2 %0,%1,%2;" : "=l"(r) : "l"(a), "l"(b)); return r;
}
__device__ __forceinline__ u64 add2(u64 a, u64 b) {
    u64 r; asm("add.rn.f32x2 %0,%1,%2;" : "=l"(r) : "l"(a), "l"(b)); return r;
}
__device__ __forceinline__ u64 fma2(u64 a, u64 b, u64 c) {
    u64 r; asm("fma.rn.f32x2 %0,%1,%2,%3;" : "=l"(r) : "l"(a), "l"(b), "l"(c)); return r;
}

// ---------------------------------------------------------------------------
// Kernel 1: copy values -> out[0:N] rows, build all 4N coordinate rows.
// ---------------------------------------------------------------------------
__global__ void setup_kernel(const float4* __restrict__ val4,
                             const float2* __restrict__ c2,
                             const float*  __restrict__ spacing,
                             float*        __restrict__ out)
{
    int tid    = blockIdx.x * blockDim.x + threadIdx.x;
    int stride = gridDim.x * blockDim.x;

    float4* outv4 = reinterpret_cast<float4*>(out);
    for (int i = tid; i < N_PTS * C4; i += stride)
        outv4[i] = __ldg(&val4[i]);

    float s0 = __ldg(&spacing[0]);
    float s1 = __ldg(&spacing[1]);
    float2* outc = reinterpret_cast<float2*>(out + VOFF);
    for (int i = tid; i < N_PTS; i += stride) {
        float2 c = __ldg(&c2[i]);
        float xs = __fadd_rn(c.x, s0);
        float ys = __fadd_rn(c.y, s1);
        outc[i]             = c;
        outc[N_PTS   + i]   = make_float2(xs,  ys);
        outc[2*N_PTS + i]   = make_float2(c.x, ys);
        outc[3*N_PTS + i]   = make_float2(xs,  c.y);
    }
}

extern __shared__ float smem_dyn[];

// ---------------------------------------------------------------------------
// Kernel 2: segmented brute-force argmin. CTA b: seg = b/96, queries
// (b%96)*256 + tid. Each thread owns one query and scans its CTA's segment
// (points staged in 16.4 KB smem, warp-uniform j -> broadcast LDS.128).
// d2 = RN( RN(sa+sc) - 2m ), m = fma(a1,c1, RN(a0*c0))  [bit-exact vs ref].
// ---------------------------------------------------------------------------
__global__ void __launch_bounds__(TPB, 4)
argmin_kernel(const float2* __restrict__ c2,
              const float*  __restrict__ spacing,
              const float*  __restrict__ shift)
{
    float* c0 = smem_dyn;
    float* c1 = c0 + SEGSZ;
    float* sc = c1 + SEGSZ;

    const int seg  = blockIdx.x / QCTA;
    const int sbeg = seg * SEGSZ;
    const int slen = (seg == NSEG - 1) ? (N_PTS - sbeg) : SEGSZ;

    // Stage this segment's coords + |c|^2 (mul,mul,add order per reference).
    for (int i = threadIdx.x; i < slen; i += TPB) {
        float2 c = __ldg(&c2[sbeg + i]);
        c0[i] = c.x;
        c1[i] = c.y;
        sc[i] = __fadd_rn(__fmul_rn(c.x, c.x), __fmul_rn(c.y, c.y));
    }
    __syncthreads();

    const int q = (blockIdx.x % QCTA) * TPB + threadIdx.x;   // 0..24575
    const int g = q >> 13;                                    // shifted-copy id
    const int i = q & (N_PTS - 1);

    float2 c  = __ldg(&c2[i]);
    float s0  = __ldg(&spacing[0]), s1  = __ldg(&spacing[1]);
    float sh0 = __ldg(&shift[0]),   sh1 = __ldg(&shift[1]);

    float nc0, nc1;
    if (g == 0)      { nc0 = __fadd_rn(c.x, s0); nc1 = __fadd_rn(c.y, s1); }
    else if (g == 1) { nc0 = c.x;                nc1 = __fadd_rn(c.y, s1); }
    else             { nc0 = __fadd_rn(c.x, s0); nc1 = c.y;                }

    float a0 = __fsub_rn(nc0, sh0);
    float a1 = __fsub_rn(nc1, sh1);
    float sa = __fadd_rn(__fmul_rn(a0, a0), __fmul_rn(a1, a1));

    const u64 A0 = pk2(a0, a0);
    const u64 A1 = pk2(a1, a1);
    const u64 SA = pk2(sa, sa);
    const u64 N2 = pk2(-2.0f, -2.0f);

    float bd = __int_as_float(0x7f800000);   // +inf
    int   bj = sbeg;

    #pragma unroll 1
    for (int j = 0; j < slen; j += 8) {
        const ulonglong2 X0 = *reinterpret_cast<const ulonglong2*>(c0 + j);
        const ulonglong2 Y0 = *reinterpret_cast<const ulonglong2*>(c1 + j);
        const ulonglong2 Z0 = *reinterpret_cast<const ulonglong2*>(sc + j);
        u64 d01 = fma2(fma2(A1, Y0.x, mul2(A0, X0.x)), N2, add2(SA, Z0.x));
        u64 d23 = fma2(fma2(A1, Y0.y, mul2(A0, X0.y)), N2, add2(SA, Z0.y));
        const ulonglong2 X1 = *reinterpret_cast<const ulonglong2*>(c0 + j + 4);
        const ulonglong2 Y1 = *reinterpret_cast<const ulonglong2*>(c1 + j + 4);
        const ulonglong2 Z1 = *reinterpret_cast<const ulonglong2*>(sc + j + 4);
        u64 d45 = fma2(fma2(A1, Y1.x, mul2(A0, X1.x)), N2, add2(SA, Z1.x));
        u64 d67 = fma2(fma2(A1, Y1.y, mul2(A0, X1.y)), N2, add2(SA, Z1.y));

        float d0, d1, d2v, d3v, d4v, d5v, d6v, d7v;
        upk2(d0,  d1,  d01);
        upk2(d2v, d3v, d23);
        upk2(d4v, d5v, d45);
        upk2(d6v, d7v, d67);

        // 8-way tournament; strict '<' + ascending indices = first-min wins.
        bool p01 = d1  < d0;   float e0 = p01 ? d1  : d0;   int k0 = p01 ? 1 : 0;
        bool p23 = d3v < d2v;  float e1 = p23 ? d3v : d2v;  int k1 = p23 ? 3 : 2;
        bool p45 = d5v < d4v;  float e2 = p45 ? d5v : d4v;  int k2 = p45 ? 5 : 4;
        bool p67 = d7v < d6v;  float e3 = p67 ? d7v : d6v;  int k3 = p67 ? 7 : 6;
        bool q0  = e1 < e0;    float f0 = q0 ? e1 : e0;     int l0 = q0 ? k1 : k0;
        bool q1  = e3 < e2;    float f1 = q1 ? e3 : e2;     int l1 = q1 ? k3 : k2;
        bool w0  = f1 < f0;    float gd = w0 ? f1 : f0;     int gk = w0 ? l1 : l0;

        bool pw = gd < bd;
        bd = pw ? gd : bd;
        bj = pw ? (sbeg + j + gk) : bj;
    }

    g_pd[seg * NQ + q] = bd;
    g_pj[seg * NQ + q] = bj;
}

// ---------------------------------------------------------------------------
// Kernel 3: reduce 6 segment partials per query (ascending seg order, strict
// '<' -> first-occurrence argmin) + gather the 64-float value rows.
// Block = 256 threads over 128 queries.
// ---------------------------------------------------------------------------
__global__ void __launch_bounds__(TPB)
reduce_gather_kernel(const float4* __restrict__ val4,
                     float*        __restrict__ out)
{
    __shared__ int widx[128];
    const int qbase = blockIdx.x * 128;

    if (threadIdx.x < 128) {
        int q = qbase + threadIdx.x;
        float bd = g_pd[q];
        int   bj = g_pj[q];
        #pragma unroll
        for (int s = 1; s < NSEG; s++) {
            float d = g_pd[s * NQ + q];
            int   j = g_pj[s * NQ + q];
            if (d < bd) { bd = d; bj = j; }
        }
        widx[threadIdx.x] = bj;
    }
    __syncthreads();

    float4* outv4 = reinterpret_cast<float4*>(out);
    #pragma unroll
    for (int t = threadIdx.x; t < 128 * C4; t += TPB) {
        int rr = t >> 4;
        int cc = t & (C4 - 1);
        outv4[(size_t)(N_PTS + qbase + rr) * C4 + cc] =
            __ldg(&val4[(size_t)widx[rr] * C4 + cc]);
    }
}

// ---------------------------------------------------------------------------
extern "C" void kernel_launch(void* const* d_in, const int* in_sizes, int n_in,
                              void* d_out, int out_size)
{
    const float4* val4    = (const float4*)d_in[0];
    const float2* c2      = (const float2*)d_in[1];
    const float*  spacing = (const float*) d_in[2];
    const float*  shift   = (const float*) d_in[3];
    float* out = (float*)d_out;

    argmin_kernel<<<GRID1, TPB, SMEM1>>>(c2, spacing, shift);
    setup_kernel<<<256, TPB>>>(val4, c2, spacing, out);
    reduce_gather_kernel<<<NQ / 128, TPB>>>(val4, out);
}

// round 7
// speedup vs baseline: 2.3204x; 1.2427x over previous
#include <cuda_runtime.h>

#define N_PTS   8192
#define C_DIM   64
#define C4      (C_DIM/4)
#define NQ      (3*N_PTS)                 // 24576 queries
#define VOFF    ((size_t)4*N_PTS*C_DIM)   // float offset of out_coords

#define TPB     256
#define NSEG    9
#define SEGSZ   912                       // segs 0..7 = 912 pts, seg 8 = 896
#define QCTA    (NQ/TPB)                  // 96 CTAs per segment
#define GRID1   (NSEG*QCTA)               // 864 CTAs = one wave at 6/SM
#define SMEM1   (3*SEGSZ*4)               // 10944 B

typedef unsigned long long u64;

// Cross-CTA partial argmin scratch.
__device__ float g_pd[NSEG * NQ];
__device__ int   g_pj[NSEG * NQ];

// ---------------- packed f32x2 helpers (IEEE RN per lane) -------------------
__device__ __forceinline__ u64 pk2(float lo, float hi) {
    u64 r; asm("mov.b64 %0,{%1,%2};" : "=l"(r) : "f"(lo), "f"(hi)); return r;
}
__device__ __forceinline__ void upk2(float& lo, float& hi, u64 v) {
    asm("mov.b64 {%0,%1},%2;" : "=f"(lo), "=f"(hi) : "l"(v));
}
__device__ __forceinline__ u64 mul2(u64 a, u64 b) {
    u64 r; asm("mul.rn.f32x2 %0,%1,%2;" : "=l"(r) : "l"(a), "l"(b)); return r;
}
__device__ __forceinline__ u64 add2(u64 a, u64 b) {
    u64 r; asm("add.rn.f32x2 %0,%1,%2;" : "=l"(r) : "l"(a), "l"(b)); return r;
}
__device__ __forceinline__ u64 fma2(u64 a, u64 b, u64 c) {
    u64 r; asm("fma.rn.f32x2 %0,%1,%2,%3;" : "=l"(r) : "l"(a), "l"(b), "l"(c)); return r;
}

// d2 for 8 consecutive staged points, bit-exact vs reference:
//   d = RN( RN(sa+sc) - 2m ),  m = fma(a1,c1, RN(a0*c0))
__device__ __forceinline__ void dist8(const float* __restrict__ c0,
                                      const float* __restrict__ c1,
                                      const float* __restrict__ sc,
                                      int j, u64 A0, u64 A1, u64 SA, u64 N2,
                                      float* d)
{
    const ulonglong2 X0 = *reinterpret_cast<const ulonglong2*>(c0 + j);
    const ulonglong2 Y0 = *reinterpret_cast<const ulonglong2*>(c1 + j);
    const ulonglong2 Z0 = *reinterpret_cast<const ulonglong2*>(sc + j);
    const ulonglong2 X1 = *reinterpret_cast<const ulonglong2*>(c0 + j + 4);
    const ulonglong2 Y1 = *reinterpret_cast<const ulonglong2*>(c1 + j + 4);
    const ulonglong2 Z1 = *reinterpret_cast<const ulonglong2*>(sc + j + 4);
    u64 d01 = fma2(fma2(A1, Y0.x, mul2(A0, X0.x)), N2, add2(SA, Z0.x));
    u64 d23 = fma2(fma2(A1, Y0.y, mul2(A0, X0.y)), N2, add2(SA, Z0.y));
    u64 d45 = fma2(fma2(A1, Y1.x, mul2(A0, X1.x)), N2, add2(SA, Z1.x));
    u64 d67 = fma2(fma2(A1, Y1.y, mul2(A0, X1.y)), N2, add2(SA, Z1.y));
    upk2(d[0], d[1], d01);
    upk2(d[2], d[3], d23);
    upk2(d[4], d[5], d45);
    upk2(d[6], d[7], d67);
}

extern __shared__ float smem_dyn[];

// ---------------------------------------------------------------------------
// Kernel 1: segmented brute-force argmin. CTA b: seg = b/QCTA, query =
// (b%QCTA)*TPB + tid. Value-only FMNMX min in the hot loop; the winning
// iteration's slot index is recovered bit-exactly in a one-shot epilogue.
// ---------------------------------------------------------------------------
__global__ void __launch_bounds__(TPB, 6)
argmin_kernel(const float2* __restrict__ c2,
              const float*  __restrict__ spacing,
              const float*  __restrict__ shift)
{
    float* c0 = smem_dyn;
    float* c1 = c0 + SEGSZ;
    float* sc = c1 + SEGSZ;

    const int seg  = blockIdx.x / QCTA;
    const int sbeg = seg * SEGSZ;
    const int slen = (seg == NSEG - 1) ? (N_PTS - sbeg) : SEGSZ;

    // Stage coords + |c|^2 (mul, mul, add order per reference).
    for (int i = threadIdx.x; i < slen; i += TPB) {
        float2 c = __ldg(&c2[sbeg + i]);
        c0[i] = c.x;
        c1[i] = c.y;
        sc[i] = __fadd_rn(__fmul_rn(c.x, c.x), __fmul_rn(c.y, c.y));
    }
    __syncthreads();

    const int q = (blockIdx.x % QCTA) * TPB + threadIdx.x;   // 0..24575
    const int g = q >> 13;
    const int i = q & (N_PTS - 1);

    float2 c  = __ldg(&c2[i]);
    float s0  = __ldg(&spacing[0]), s1  = __ldg(&spacing[1]);
    float sh0 = __ldg(&shift[0]),   sh1 = __ldg(&shift[1]);

    float nc0, nc1;
    if (g == 0)      { nc0 = __fadd_rn(c.x, s0); nc1 = __fadd_rn(c.y, s1); }
    else if (g == 1) { nc0 = c.x;                nc1 = __fadd_rn(c.y, s1); }
    else             { nc0 = __fadd_rn(c.x, s0); nc1 = c.y;                }

    float a0 = __fsub_rn(nc0, sh0);
    float a1 = __fsub_rn(nc1, sh1);
    float sa = __fadd_rn(__fmul_rn(a0, a0), __fmul_rn(a1, a1));

    const u64 A0 = pk2(a0, a0);
    const u64 A1 = pk2(a1, a1);
    const u64 SA = pk2(sa, sa);
    const u64 N2 = pk2(-2.0f, -2.0f);

    float bd   = __int_as_float(0x7f800000);   // +inf
    int   bjit = 0;                             // winning iteration offset

    #pragma unroll 1
    for (int j = 0; j < slen; j += 8) {
        float d[8];
        dist8(c0, c1, sc, j, A0, A1, SA, N2, d);

        // Pure value min: 7 FMNMX.
        float m01 = fminf(d[0], d[1]);
        float m23 = fminf(d[2], d[3]);
        float m45 = fminf(d[4], d[5]);
        float m67 = fminf(d[6], d[7]);
        float m03 = fminf(m01, m23);
        float m47 = fminf(m45, m67);
        float gd  = fminf(m03, m47);

        // Strict '<' -> earliest iteration wins ties.
        bool pw = gd < bd;
        bd   = fminf(bd, gd);
        bjit = pw ? j : bjit;
    }

    // Epilogue: recover the first slot within the winning iteration whose
    // (bit-identically recomputed) distance equals bd. Descending scan with
    // '==' leaves the SMALLEST matching slot -> first-occurrence argmin.
    {
        float d[8];
        dist8(c0, c1, sc, bjit, A0, A1, SA, N2, d);
        int slot = 7;
        #pragma unroll
        for (int k = 6; k >= 0; k--)
            slot = (d[k] == bd) ? k : slot;

        g_pd[seg * NQ + q] = bd;
        g_pj[seg * NQ + q] = sbeg + bjit + slot;
    }
}

// ---------------------------------------------------------------------------
// Kernel 2 (finalize): reduce NSEG partials per query (ascending seg order,
// strict '<' -> first occurrence), gather winner value rows, copy original
// values, and build all 4N coordinate rows. Grid = NQ/128 = 192 CTAs.
// ---------------------------------------------------------------------------
__global__ void __launch_bounds__(TPB)
finalize_kernel(const float4* __restrict__ val4,
                const float2* __restrict__ c2,
                const float*  __restrict__ spacing,
                float*        __restrict__ out)
{
    __shared__ int widx[128];
    const int qbase = blockIdx.x * 128;

    if (threadIdx.x < 128) {
        int q = qbase + threadIdx.x;
        float bd = g_pd[q];
        int   bj = g_pj[q];
        #pragma unroll
        for (int s = 1; s < NSEG; s++) {
            float d = g_pd[s * NQ + q];
            int   j = g_pj[s * NQ + q];
            if (d < bd) { bd = d; bj = j; }
        }
        widx[threadIdx.x] = bj;
    }
    __syncthreads();

    float4* outv4 = reinterpret_cast<float4*>(out);

    // Gather: values[widx[r]] -> out rows [N_PTS + qbase, +128).
    #pragma unroll
    for (int t = threadIdx.x; t < 128 * C4; t += TPB) {
        int rr = t >> 4;
        int cc = t & (C4 - 1);
        outv4[(size_t)(N_PTS + qbase + rr) * C4 + cc] =
            __ldg(&val4[(size_t)widx[rr] * C4 + cc]);
    }

    // Copy original values (grid-strided across all CTAs).
    const int tid    = blockIdx.x * TPB + threadIdx.x;
    const int stride = gridDim.x * TPB;
    for (int t = tid; t < N_PTS * C4; t += stride)
        outv4[t] = __ldg(&val4[t]);

    // Build out_coords: original + 3 shifted copies.
    float s0 = __ldg(&spacing[0]);
    float s1 = __ldg(&spacing[1]);
    float2* outc = reinterpret_cast<float2*>(out + VOFF);
    for (int t = tid; t < N_PTS; t += stride) {
        float2 cc = __ldg(&c2[t]);
        float xs = __fadd_rn(cc.x, s0);
        float ys = __fadd_rn(cc.y, s1);
        outc[t]             = cc;
        outc[N_PTS   + t]   = make_float2(xs,   ys);
        outc[2*N_PTS + t]   = make_float2(cc.x, ys);
        outc[3*N_PTS + t]   = make_float2(xs,   cc.y);
    }
}

// ---------------------------------------------------------------------------
extern "C" void kernel_launch(void* const* d_in, const int* in_sizes, int n_in,
                              void* d_out, int out_size)
{
    const float4* val4    = (const float4*)d_in[0];
    const float2* c2      = (const float2*)d_in[1];
    const float*  spacing = (const float*) d_in[2];
    const float*  shift   = (const float*) d_in[3];
    float* out = (float*)d_out;

    argmin_kernel<<<GRID1, TPB, SMEM1>>>(c2, spacing, shift);
    finalize_kernel<<<NQ / 128, TPB>>>(val4, c2, spacing, out);
}

// round 8
// speedup vs baseline: 2.3340x; 1.0059x over previous
#include <cuda_runtime.h>

#define N_PTS   8192
#define C_DIM   64
#define C4      (C_DIM/4)
#define NQ      (3*N_PTS)                 // 24576 queries
#define VOFF    ((size_t)4*N_PTS*C_DIM)   // float offset of out_coords

#define TPB     256
#define NSEG    9
#define SEGSZ   912                       // segs 0..7 = 912 pts, seg 8 = 896
#define QCTA    (NQ/TPB)                  // 96 CTAs per segment
#define GRID1   (NSEG*QCTA)               // 864 CTAs = one wave at 6/SM
#define SMEM1   (3*SEGSZ*4)               // 10944 B

typedef unsigned long long u64;
typedef unsigned int       u32;

// Per-query packed (ordered_d_bits << 32) | index, reduced via atomicMin.
__device__ u64 g_key[NQ];

// ---------------- packed f32x2 helpers (IEEE RN per lane) -------------------
__device__ __forceinline__ u64 pk2(float lo, float hi) {
    u64 r; asm("mov.b64 %0,{%1,%2};" : "=l"(r) : "f"(lo), "f"(hi)); return r;
}
__device__ __forceinline__ void upk2(float& lo, float& hi, u64 v) {
    asm("mov.b64 {%0,%1},%2;" : "=f"(lo), "=f"(hi) : "l"(v));
}
__device__ __forceinline__ u64 mul2(u64 a, u64 b) {
    u64 r; asm("mul.rn.f32x2 %0,%1,%2;" : "=l"(r) : "l"(a), "l"(b)); return r;
}
__device__ __forceinline__ u64 add2(u64 a, u64 b) {
    u64 r; asm("add.rn.f32x2 %0,%1,%2;" : "=l"(r) : "l"(a), "l"(b)); return r;
}
__device__ __forceinline__ u64 fma2(u64 a, u64 b, u64 c) {
    u64 r; asm("fma.rn.f32x2 %0,%1,%2,%3;" : "=l"(r) : "l"(a), "l"(b), "l"(c)); return r;
}

// d2 for 8 consecutive staged points, bit-exact vs reference:
//   d = RN( RN(sa+sc) - 2m ),  m = fma(a1,c1, RN(a0*c0))
__device__ __forceinline__ void dist8(const float* __restrict__ c0,
                                      const float* __restrict__ c1,
                                      const float* __restrict__ sc,
                                      int j, u64 A0, u64 A1, u64 SA, u64 N2,
                                      float* d)
{
    const ulonglong2 X0 = *reinterpret_cast<const ulonglong2*>(c0 + j);
    const ulonglong2 Y0 = *reinterpret_cast<const ulonglong2*>(c1 + j);
    const ulonglong2 Z0 = *reinterpret_cast<const ulonglong2*>(sc + j);
    const ulonglong2 X1 = *reinterpret_cast<const ulonglong2*>(c0 + j + 4);
    const ulonglong2 Y1 = *reinterpret_cast<const ulonglong2*>(c1 + j + 4);
    const ulonglong2 Z1 = *reinterpret_cast<const ulonglong2*>(sc + j + 4);
    u64 d01 = fma2(fma2(A1, Y0.x, mul2(A0, X0.x)), N2, add2(SA, Z0.x));
    u64 d23 = fma2(fma2(A1, Y0.y, mul2(A0, X0.y)), N2, add2(SA, Z0.y));
    u64 d45 = fma2(fma2(A1, Y1.x, mul2(A0, X1.x)), N2, add2(SA, Z1.x));
    u64 d67 = fma2(fma2(A1, Y1.y, mul2(A0, X1.y)), N2, add2(SA, Z1.y));
    upk2(d[0], d[1], d01);
    upk2(d[2], d[3], d23);
    upk2(d[4], d[5], d45);
    upk2(d[6], d[7], d67);
}

// ---------------------------------------------------------------------------
// Kernel 1 (init + independent copies): one thread per work item, no loops.
//   t in [0, 131072)          : copy original value row float4s
//   t in [131072, 155648)     : g_key init to all-ones
//   t in [155648, 163840)     : build the 4 coordinate rows for point t-155648
// Grid = 163840/256 = 640 CTAs.
// ---------------------------------------------------------------------------
__global__ void __launch_bounds__(TPB)
init_copy_kernel(const float4* __restrict__ val4,
                 const float2* __restrict__ c2,
                 const float*  __restrict__ spacing,
                 float*        __restrict__ out)
{
    const int t = blockIdx.x * TPB + threadIdx.x;

    if (t < N_PTS * C4) {                       // 131072 value float4s
        reinterpret_cast<float4*>(out)[t] = __ldg(&val4[t]);
    } else if (t < N_PTS * C4 + NQ) {           // 24576 keys
        g_key[t - N_PTS * C4] = ~0ull;
    } else {                                    // 8192 coordinate points
        int i = t - (N_PTS * C4 + NQ);
        float2 c = __ldg(&c2[i]);
        float s0 = __ldg(&spacing[0]);
        float s1 = __ldg(&spacing[1]);
        float xs = __fadd_rn(c.x, s0);
        float ys = __fadd_rn(c.y, s1);
        float2* outc = reinterpret_cast<float2*>(out + VOFF);
        outc[i]             = c;
        outc[N_PTS   + i]   = make_float2(xs,  ys);
        outc[2*N_PTS + i]   = make_float2(c.x, ys);
        outc[3*N_PTS + i]   = make_float2(xs,  c.y);
    }
}

extern __shared__ float smem_dyn[];

// ---------------------------------------------------------------------------
// Kernel 2: segmented brute-force argmin. CTA b: seg = b/QCTA, query =
// (b%QCTA)*TPB + tid. Value-only FMNMX min in the hot loop; winning slot
// recovered bit-exactly in a one-shot epilogue; cross-segment reduction via
// packed-u64 atomicMin with exact (d, idx) lexicographic semantics.
// ---------------------------------------------------------------------------
__global__ void __launch_bounds__(TPB, 6)
argmin_kernel(const float2* __restrict__ c2,
              const float*  __restrict__ spacing,
              const float*  __restrict__ shift)
{
    float* c0 = smem_dyn;
    float* c1 = c0 + SEGSZ;
    float* sc = c1 + SEGSZ;

    const int seg  = blockIdx.x / QCTA;
    const int sbeg = seg * SEGSZ;
    const int slen = (seg == NSEG - 1) ? (N_PTS - sbeg) : SEGSZ;

    // Stage coords + |c|^2 (mul, mul, add order per reference).
    for (int i = threadIdx.x; i < slen; i += TPB) {
        float2 c = __ldg(&c2[sbeg + i]);
        c0[i] = c.x;
        c1[i] = c.y;
        sc[i] = __fadd_rn(__fmul_rn(c.x, c.x), __fmul_rn(c.y, c.y));
    }
    __syncthreads();

    const int q = (blockIdx.x % QCTA) * TPB + threadIdx.x;   // 0..24575
    const int g = q >> 13;
    const int i = q & (N_PTS - 1);

    float2 c  = __ldg(&c2[i]);
    float s0  = __ldg(&spacing[0]), s1  = __ldg(&spacing[1]);
    float sh0 = __ldg(&shift[0]),   sh1 = __ldg(&shift[1]);

    float nc0, nc1;
    if (g == 0)      { nc0 = __fadd_rn(c.x, s0); nc1 = __fadd_rn(c.y, s1); }
    else if (g == 1) { nc0 = c.x;                nc1 = __fadd_rn(c.y, s1); }
    else             { nc0 = __fadd_rn(c.x, s0); nc1 = c.y;                }

    float a0 = __fsub_rn(nc0, sh0);
    float a1 = __fsub_rn(nc1, sh1);
    float sa = __fadd_rn(__fmul_rn(a0, a0), __fmul_rn(a1, a1));

    const u64 A0 = pk2(a0, a0);
    const u64 A1 = pk2(a1, a1);
    const u64 SA = pk2(sa, sa);
    const u64 N2 = pk2(-2.0f, -2.0f);

    float bd   = __int_as_float(0x7f800000);   // +inf
    int   bjit = 0;                             // winning iteration offset

    #pragma unroll 2
    for (int j = 0; j < slen; j += 8) {
        float d[8];
        dist8(c0, c1, sc, j, A0, A1, SA, N2, d);

        // Pure value min: 7 FMNMX.
        float m01 = fminf(d[0], d[1]);
        float m23 = fminf(d[2], d[3]);
        float m45 = fminf(d[4], d[5]);
        float m67 = fminf(d[6], d[7]);
        float m03 = fminf(m01, m23);
        float m47 = fminf(m45, m67);
        float gd  = fminf(m03, m47);

        // Strict '<' -> earliest iteration wins ties.
        bool pw = gd < bd;
        bd   = fminf(bd, gd);
        bjit = pw ? j : bjit;
    }

    // Epilogue: first slot in the winning iteration whose bit-identically
    // recomputed distance equals bd (descending '==' scan -> smallest slot).
    float d[8];
    dist8(c0, c1, sc, bjit, A0, A1, SA, N2, d);
    int slot = 7;
    #pragma unroll
    for (int k = 6; k >= 0; k--)
        slot = (d[k] == bd) ? k : slot;

    // Pack (ordered d bits, index) and atomically min-reduce across segments.
    // Ordered transform is strictly monotone -> exact (d, idx) lexicographic
    // min == jnp.argmin first-occurrence. (-0.0 cannot occur: RN cancellation
    // yields +0.)
    u32 ub = __float_as_uint(bd);
    ub = (ub & 0x80000000u) ? ~ub : (ub | 0x80000000u);
    u64 key = ((u64)ub << 32) | (u32)(sbeg + bjit + slot);
    atomicMin(&g_key[q], key);
}

// ---------------------------------------------------------------------------
// Kernel 3: gather. One thread per output float4 of the new-value region.
// Grid = 24576*16/256 = 1536 CTAs.
// ---------------------------------------------------------------------------
__global__ void __launch_bounds__(TPB)
gather_kernel(const float4* __restrict__ val4,
              float*        __restrict__ out)
{
    const int t   = blockIdx.x * TPB + threadIdx.x;   // 0..393215
    const int row = t >> 4;                            // query id
    const int cc  = t & (C4 - 1);
    const int idx = (int)(u32)(g_key[row] & 0xFFFFFFFFull);
    reinterpret_cast<float4*>(out)[(size_t)(N_PTS + row) * C4 + cc] =
        __ldg(&val4[(size_t)idx * C4 + cc]);
}

// ---------------------------------------------------------------------------
extern "C" void kernel_launch(void* const* d_in, const int* in_sizes, int n_in,
                              void* d_out, int out_size)
{
    const float4* val4    = (const float4*)d_in[0];
    const float2* c2      = (const float2*)d_in[1];
    const float*  spacing = (const float*) d_in[2];
    const float*  shift   = (const float*) d_in[3];
    float* out = (float*)d_out;

    init_copy_kernel<<<(N_PTS * C4 + NQ + N_PTS) / TPB, TPB>>>(val4, c2,
                                                               spacing, out);
    argmin_kernel<<<GRID1, TPB, SMEM1>>>(c2, spacing, shift);
    gather_kernel<<<NQ * C4 / TPB, TPB>>>(val4, out);
}